// round 1
// baseline (speedup 1.0000x reference)
#include <cuda_runtime.h>

typedef unsigned long long ull;

// packed fp32x2 FMA: d = a*b + d (2 FLOPs/lane-slot; only reachable via PTX)
#define FMA2(d, a, b) asm("fma.rn.f32x2 %0, %1, %2, %0;" : "+l"(d) : "l"(a), "l"(b))

// scratch: v[b][s*64+o][h][w] = sum_c Wf[o, s*64+c] * x[b][c][h][w]
// 8 * 192 * 256 * 256 floats = 384 MB (__device__ global: allocation-rule safe)
__device__ float g_v[100663296];

// ---------------------------------------------------------------------------
// Kernel 1: per-pixel channel GEMM  v[m] = sum_k A[m][k] * x[k],  m = s*64+o
// Block: 64 pixels x all 192 outputs. 192 threads, each 8 m-rows x 8 pixels.
// ---------------------------------------------------------------------------
__global__ __launch_bounds__(192) void gemm_kernel(
    const float* __restrict__ x, const float* __restrict__ wf) {
  extern __shared__ float smem[];
  float* sA = smem;             // [64][192]: sA[k*192 + m], m = s*64+o
  float* sB = smem + 64 * 192;  // [64][64] : x tile

  const int t = threadIdx.x;
  const int q0 = blockIdx.x * 64;     // first flat pixel (b, h*256+w)
  const int b = q0 >> 16;
  const int pp0 = q0 & 65535;

  // weights: wf[o*192 + s*64 + k] -> sA[k*192 + s*64 + o]  (coalesced gmem read)
  for (int u = t; u < 12288; u += 192) {
    const int o = u / 192;
    const int j = u - o * 192;        // j = s*64 + k
    const int s = j >> 6, k = j & 63;
    sA[k * 192 + (s << 6) + o] = wf[u];
  }
  // x tile: 64 channels x 64 consecutive pixels
  const float* xb = x + (size_t)(b << 6) * 65536 + pp0;
  for (int i = t; i < 4096; i += 192) {
    const int k = i >> 6, p = i & 63;
    sB[i] = xb[(size_t)k * 65536 + p];
  }
  __syncthreads();

  const int mg = t >> 3, pg = t & 7;
  const int m0 = mg << 3;             // 24 groups * 8 = 192 output rows
  const int p0 = pg << 3;             // 8 groups * 8 = 64 pixels

  ull acc[4][8];                      // 4 m-pairs (f32x2 over m) x 8 pixels
  #pragma unroll
  for (int i = 0; i < 4; i++)
    #pragma unroll
    for (int j = 0; j < 8; j++) acc[i][j] = 0ULL;

  #pragma unroll 4
  for (int k = 0; k < 64; ++k) {
    const float* Ak = sA + k * 192 + m0;
    ull a[4];
    a[0] = *(const ull*)(Ak + 0);     // (m0,m0+1) .. 8B-aligned (m0 % 8 == 0)
    a[1] = *(const ull*)(Ak + 2);
    a[2] = *(const ull*)(Ak + 4);
    a[3] = *(const ull*)(Ak + 6);
    const float* Bk = sB + (k << 6) + p0;
    const float4 q0v = *(const float4*)(Bk);
    const float4 q1v = *(const float4*)(Bk + 4);
    const float bs[8] = {q0v.x, q0v.y, q0v.z, q0v.w, q1v.x, q1v.y, q1v.z, q1v.w};
    ull b2[8];
    #pragma unroll
    for (int p = 0; p < 8; p++) {
      union { float2 f; ull u; } cv;
      cv.f = make_float2(bs[p], bs[p]);   // broadcast pixel into both halves
      b2[p] = cv.u;
    }
    #pragma unroll
    for (int mp = 0; mp < 4; mp++)
      #pragma unroll
      for (int p = 0; p < 8; p++)
        FMA2(acc[mp][p], a[mp], b2[p]);
  }

  // store: unpack m-pairs, write per-row float4s (coalesced across pg lanes)
  float* vb = g_v + (size_t)b * 192 * 65536 + pp0 + p0;
  #pragma unroll
  for (int mp = 0; mp < 4; mp++) {
    float lo[8], hi[8];
    #pragma unroll
    for (int p = 0; p < 8; p++) {
      union { ull u; float2 f; } cv;
      cv.u = acc[mp][p];
      lo[p] = cv.f.x; hi[p] = cv.f.y;
    }
    const int m = m0 + 2 * mp;
    float4* d0 = (float4*)(vb + (size_t)m * 65536);
    d0[0] = make_float4(lo[0], lo[1], lo[2], lo[3]);
    d0[1] = make_float4(lo[4], lo[5], lo[6], lo[7]);
    float4* d1 = (float4*)(vb + (size_t)(m + 1) * 65536);
    d1[0] = make_float4(hi[0], hi[1], hi[2], hi[3]);
    d1[1] = make_float4(hi[4], hi[5], hi[6], hi[7]);
  }
}

// ---------------------------------------------------------------------------
// Kernel 2: separable blur of the three v-planes for one (b, o), summed,
// + bias + residual. 32x32 output tile, halo 6 (max radius), SAME=zero-pad.
// Gaussian 1D weights (normalized, symmetric):
//   sigma 0.5 (k=3):  0.78698604 | 0.10650698
//   sigma 1.0 (k=7):  0.39905028 | 0.24203623 0.05400558 0.00443305
//   sigma 2.0 (k=13): 0.19967563 | 0.17621312 0.12110939 0.06482519
//                     0.02702316 0.00877314 0.00221820
// ---------------------------------------------------------------------------
__global__ __launch_bounds__(256) void blur_kernel(
    const float* __restrict__ x, const float* __restrict__ fb,
    float* __restrict__ out) {
  __shared__ float sv[3][44][45];   // raw v tiles (+halo), padded stride
  __shared__ float hb[3][44][32];   // after horizontal pass

  const int t = threadIdx.x;
  const int bo = blockIdx.z;
  const int b = bo >> 6, o = bo & 63;
  const int h0 = blockIdx.y << 5, w0 = blockIdx.x << 5;

  const float* vbase = g_v + ((size_t)b * 192 + o) * 65536;
  #pragma unroll
  for (int s = 0; s < 3; s++) {
    const float* vp = vbase + (size_t)(s << 6) * 65536;
    for (int i = t; i < 44 * 44; i += 256) {
      const int r = i / 44, c = i - r * 44;
      const int hh = h0 - 6 + r, ww = w0 - 6 + c;
      float val = 0.f;
      if ((unsigned)hh < 256u && (unsigned)ww < 256u) val = vp[hh * 256 + ww];
      sv[s][r][c] = val;
    }
  }
  __syncthreads();

  // horizontal pass (center at col j+6)
  for (int i = t; i < 44 * 32; i += 256) {
    const int r = i >> 5, j = i & 31;
    const float* p0r = &sv[0][r][j];
    hb[0][r][j] = 0.78698604f * p0r[6] + 0.10650698f * (p0r[5] + p0r[7]);
    const float* p1r = &sv[1][r][j];
    hb[1][r][j] = 0.39905028f * p1r[6]
                + 0.24203623f * (p1r[5] + p1r[7])
                + 0.05400558f * (p1r[4] + p1r[8])
                + 0.00443305f * (p1r[3] + p1r[9]);
    const float* p2r = &sv[2][r][j];
    hb[2][r][j] = 0.19967563f * p2r[6]
                + 0.17621312f * (p2r[5] + p2r[7])
                + 0.12110939f * (p2r[4] + p2r[8])
                + 0.06482519f * (p2r[3] + p2r[9])
                + 0.02702316f * (p2r[2] + p2r[10])
                + 0.00877314f * (p2r[1] + p2r[11])
                + 0.00221820f * (p2r[0] + p2r[12]);
  }
  __syncthreads();

  // vertical pass + combine + bias + residual
  const float bias = fb[o];
  const float* xp = x + ((size_t)(b << 6) + o) * 65536;
  float* op = out + ((size_t)(b << 6) + o) * 65536;
  for (int i = t; i < 1024; i += 256) {
    const int ii = i >> 5, j = i & 31;
    float acc = bias + xp[(h0 + ii) * 256 + w0 + j];
    acc += 0.78698604f * hb[0][ii + 6][j]
         + 0.10650698f * (hb[0][ii + 5][j] + hb[0][ii + 7][j]);
    acc += 0.39905028f * hb[1][ii + 6][j]
         + 0.24203623f * (hb[1][ii + 5][j] + hb[1][ii + 7][j])
         + 0.05400558f * (hb[1][ii + 4][j] + hb[1][ii + 8][j])
         + 0.00443305f * (hb[1][ii + 3][j] + hb[1][ii + 9][j]);
    acc += 0.19967563f * hb[2][ii + 6][j]
         + 0.17621312f * (hb[2][ii + 5][j] + hb[2][ii + 7][j])
         + 0.12110939f * (hb[2][ii + 4][j] + hb[2][ii + 8][j])
         + 0.06482519f * (hb[2][ii + 3][j] + hb[2][ii + 9][j])
         + 0.02702316f * (hb[2][ii + 2][j] + hb[2][ii + 10][j])
         + 0.00877314f * (hb[2][ii + 1][j] + hb[2][ii + 11][j])
         + 0.00221820f * (hb[2][ii + 0][j] + hb[2][ii + 12][j]);
    op[(h0 + ii) * 256 + w0 + j] = acc;
  }
}

// ---------------------------------------------------------------------------
extern "C" void kernel_launch(void* const* d_in, const int* in_sizes, int n_in,
                              void* d_out, int out_size) {
  const float* x  = (const float*)d_in[0];   // [8,64,256,256] f32
  const float* wf = (const float*)d_in[1];   // [64,192] f32
  const float* fb = (const float*)d_in[2];   // [64] f32
  float* out = (float*)d_out;                // [8,64,256,256] f32

  cudaFuncSetAttribute(gemm_kernel,
                       cudaFuncAttributeMaxDynamicSharedMemorySize, 65536);
  gemm_kernel<<<8192, 192, 65536>>>(x, wf);

  dim3 g2(8, 8, 512);  // (w-tiles, h-tiles, b*64+o)
  blur_kernel<<<g2, 256>>>(x, fb, out);
}

// round 3
// speedup vs baseline: 2.6867x; 2.6867x over previous
#include <cuda_runtime.h>

typedef unsigned long long ull;

// packed fp32x2 FMA: d = a*b + d (PTX-only pattern; 2 MACs per lane-slot)
#define FMA2(d, a, b) asm("fma.rn.f32x2 %0, %1, %2, %0;" : "+l"(d) : "l"(a), "l"(b))

// scratch: y[b][s*64+c][h][w] = Blur_s(x[b][c])   (8*192*256*256 f32 = 384 MB)
__device__ float g_v[100663296];
// transposed fusion weights: g_wt[k*64 + o] = wf[o*192 + k], k = s*64+c
__device__ float g_wt[12288];

__device__ __forceinline__ ull bcast2(float v) {
  union { float2 f; ull u; } c;
  c.f.x = v; c.f.y = v;
  return c.u;
}

// ---------------------------------------------------------------------------
// Kernel 0: one-time weight transpose (coalesced read, 4B scatter write)
// ---------------------------------------------------------------------------
__global__ void wt_kernel(const float* __restrict__ wf) {
  int i = blockIdx.x * 256 + threadIdx.x;   // i = o*192 + j
  if (i < 12288) {
    int o = i / 192, j = i - o * 192;
    g_wt[j * 64 + o] = wf[i];
  }
}

// ---------------------------------------------------------------------------
// Kernel 1: separable 3-scale blur. One (b,c) plane, 64x64 output tile.
// x tile (+halo 6) loaded ONCE, shared by all three scales.
// Horizontal pass shares the 13-tap read across scales; vertical pass uses
// register-sliding windows (3 new LDS per output row instead of 23).
// ---------------------------------------------------------------------------
__global__ __launch_bounds__(256) void blur_kernel(const float* __restrict__ x) {
  extern __shared__ float sm[];
  float* sv = sm;               // [76][77] raw x tile (+halo), padded stride
  float* hb = sm + 76 * 77;     // [3][76][64] after horizontal pass

  const int t = threadIdx.x;
  const int pl = blockIdx.z;    // b*64 + c
  const int b = pl >> 6, c = pl & 63;
  const int h0 = blockIdx.y << 6, w0 = blockIdx.x << 6;
  const float* xp = x + (size_t)pl * 65536;

  // load 76x76 halo tile, zero-pad (SAME)
  for (int i = t; i < 5776; i += 256) {
    const int r = i / 76, cc = i - r * 76;
    const int hh = h0 - 6 + r, ww = w0 - 6 + cc;
    float v = 0.f;
    if ((unsigned)hh < 256u && (unsigned)ww < 256u) v = xp[hh * 256 + ww];
    sv[r * 77 + cc] = v;
  }
  __syncthreads();

  // horizontal pass: 76 rows x 64 cols, 13 shared reads feed all 3 scales
  for (int i = t; i < 4864; i += 256) {
    const int r = i >> 6, j = i & 63;
    const float* p = sv + r * 77 + j;
    const float v0 = p[0], v1 = p[1], v2 = p[2], v3 = p[3], v4 = p[4],
                v5 = p[5], v6 = p[6], v7 = p[7], v8 = p[8], v9 = p[9],
                v10 = p[10], v11 = p[11], v12 = p[12];
    hb[(0 * 76 + r) * 64 + j] = 0.78698604f * v6 + 0.10650698f * (v5 + v7);
    hb[(1 * 76 + r) * 64 + j] = 0.39905028f * v6 + 0.24203623f * (v5 + v7)
                              + 0.05400558f * (v4 + v8) + 0.00443305f * (v3 + v9);
    hb[(2 * 76 + r) * 64 + j] = 0.19967563f * v6 + 0.17621312f * (v5 + v7)
                              + 0.12110939f * (v4 + v8) + 0.06482519f * (v3 + v9)
                              + 0.02702316f * (v2 + v10) + 0.00877314f * (v1 + v11)
                              + 0.00221820f * (v0 + v12);
  }
  __syncthreads();

  // vertical pass with register-sliding windows; thread = (column j, row group)
  const int j = t & 63, rg = t >> 6;
  const int base = rg << 4;                 // 16 output rows per thread
  const size_t prow = (size_t)(h0 + base) * 256 + w0 + j;
  float* y0 = g_v + (size_t)(b * 192 + c) * 65536 + prow;
  float* y1 = g_v + (size_t)(b * 192 + 64 + c) * 65536 + prow;
  float* y2 = g_v + (size_t)(b * 192 + 128 + c) * 65536 + prow;

  float a2[13], a1[7], a0[3];
  #pragma unroll
  for (int d = 0; d < 12; d++) a2[d] = hb[(2 * 76 + base + d) * 64 + j];
  #pragma unroll
  for (int d = 0; d < 6; d++) a1[d] = hb[(1 * 76 + base + 3 + d) * 64 + j];
  a0[0] = hb[(0 * 76 + base + 5) * 64 + j];
  a0[1] = hb[(0 * 76 + base + 6) * 64 + j];

  #pragma unroll
  for (int i2 = 0; i2 < 16; i2++) {
    a2[12] = hb[(2 * 76 + base + i2 + 12) * 64 + j];
    a1[6]  = hb[(1 * 76 + base + i2 + 9) * 64 + j];
    a0[2]  = hb[(0 * 76 + base + i2 + 7) * 64 + j];
    y0[i2 * 256] = 0.78698604f * a0[1] + 0.10650698f * (a0[0] + a0[2]);
    y1[i2 * 256] = 0.39905028f * a1[3] + 0.24203623f * (a1[2] + a1[4])
                 + 0.05400558f * (a1[1] + a1[5]) + 0.00443305f * (a1[0] + a1[6]);
    y2[i2 * 256] = 0.19967563f * a2[6] + 0.17621312f * (a2[5] + a2[7])
                 + 0.12110939f * (a2[4] + a2[8]) + 0.06482519f * (a2[3] + a2[9])
                 + 0.02702316f * (a2[2] + a2[10]) + 0.00877314f * (a2[1] + a2[11])
                 + 0.00221820f * (a2[0] + a2[12]);
    #pragma unroll
    for (int d = 0; d < 12; d++) a2[d] = a2[d + 1];
    #pragma unroll
    for (int d = 0; d < 6; d++) a1[d] = a1[d + 1];
    a0[0] = a0[1]; a0[1] = a0[2];
  }
}

// ---------------------------------------------------------------------------
// Kernel 2: fused 1x1 conv (M=64, K=192) + bias + residual.
// Block: 64 pixels x 64 outputs; W (48KB) + y tile (48KB) in dyn smem (2 CTA/SM).
// Thread: 8 m-rows (4 f32x2 pairs) x 2 pixels.
// ---------------------------------------------------------------------------
__global__ __launch_bounds__(256) void fuse_kernel(
    const float* __restrict__ x, const float* __restrict__ fb,
    float* __restrict__ out) {
  extern __shared__ float sm[];
  float* sW = sm;               // [192][64]: sW[k*64 + m]
  float* sY = sm + 12288;       // [192][64]: sY[k*64 + px]

  const int t = threadIdx.x;
  const int b = blockIdx.x >> 10;
  const int p0 = (blockIdx.x & 1023) << 6;

  // stage weights (linear copy, coalesced + conflict-free)
  {
    const float4* wsrc = (const float4*)g_wt;
    float4* wdst = (float4*)sW;
    #pragma unroll
    for (int i = 0; i < 12; i++) wdst[t + i * 256] = wsrc[t + i * 256];
  }
  // stage y tile: 192 rows x 64 pixels
  {
    const float* yb = g_v + (size_t)b * 192 * 65536 + p0;
    #pragma unroll
    for (int i = 0; i < 12; i++) {
      const int idx = t + i * 256;          // 0..3071 float4 slots
      const int k = idx >> 4, f = idx & 15;
      ((float4*)(sY + k * 64))[f] = *(const float4*)(yb + (size_t)k * 65536 + f * 4);
    }
  }
  __syncthreads();

  const int pg = t & 31, mg = t >> 5;
  const int m0 = mg << 3, px = pg << 1;

  ull acc[4][2];
  #pragma unroll
  for (int i = 0; i < 4; i++) { acc[i][0] = 0ULL; acc[i][1] = 0ULL; }

  #pragma unroll 8
  for (int k = 0; k < 192; k++) {
    const ull* aw = (const ull*)(sW + k * 64 + m0);   // broadcast across warp
    const ull a0 = aw[0], a1 = aw[1], a2 = aw[2], a3 = aw[3];
    const float2 bv = *(const float2*)(sY + k * 64 + px);
    const ull b0 = bcast2(bv.x), b1 = bcast2(bv.y);
    FMA2(acc[0][0], a0, b0); FMA2(acc[1][0], a1, b0);
    FMA2(acc[2][0], a2, b0); FMA2(acc[3][0], a3, b0);
    FMA2(acc[0][1], a0, b1); FMA2(acc[1][1], a1, b1);
    FMA2(acc[2][1], a2, b1); FMA2(acc[3][1], a3, b1);
  }

  // epilogue: out = x + bias + acc  (coalesced float2 per m-row)
  const float* xb = x + (size_t)b * 64 * 65536 + p0 + px;
  float* ob = out + (size_t)b * 64 * 65536 + p0 + px;
  #pragma unroll
  for (int mp = 0; mp < 4; mp++) {
    const int m = m0 + (mp << 1);
    union { ull u; float2 f; } c0, c1;
    c0.u = acc[mp][0]; c1.u = acc[mp][1];       // (m, m+1) at px, px+1
    const float bm = __ldg(fb + m), bm1 = __ldg(fb + m + 1);
    const float2 x0 = *(const float2*)(xb + (size_t)m * 65536);
    const float2 x1 = *(const float2*)(xb + (size_t)(m + 1) * 65536);
    *(float2*)(ob + (size_t)m * 65536) =
        make_float2(x0.x + bm + c0.f.x, x0.y + bm + c1.f.x);
    *(float2*)(ob + (size_t)(m + 1) * 65536) =
        make_float2(x1.x + bm1 + c0.f.y, x1.y + bm1 + c1.f.y);
  }
}

// ---------------------------------------------------------------------------
extern "C" void kernel_launch(void* const* d_in, const int* in_sizes, int n_in,
                              void* d_out, int out_size) {
  const float* x  = (const float*)d_in[0];   // [8,64,256,256] f32
  const float* wf = (const float*)d_in[1];   // [64,192] f32
  const float* fb = (const float*)d_in[2];   // [64] f32
  float* out = (float*)d_out;                // [8,64,256,256] f32

  wt_kernel<<<48, 256>>>(wf);

  cudaFuncSetAttribute(blur_kernel,
                       cudaFuncAttributeMaxDynamicSharedMemorySize, 81776);
  blur_kernel<<<dim3(4, 4, 512), 256, 81776>>>(x);

  cudaFuncSetAttribute(fuse_kernel,
                       cudaFuncAttributeMaxDynamicSharedMemorySize, 98304);
  fuse_kernel<<<8192, 256, 98304>>>(x, fb, out);
}